// round 3
// baseline (speedup 1.0000x reference)
#include <cuda_runtime.h>
#include <cuda_bf16.h>
#include <math.h>

// Problem constants
#define HH   1024
#define BB   64
#define SS   512
#define NIN  128
#define NOUT 128

// Recurrence kernel config: 128 persistent CTAs = JCH j-chunks x KSP k-splits
#define NCTA 128
#define JCH  4      // j chunks of 256
#define KSP  32     // k splits of 32
#define JW   256    // j per CTA
#define KW   32     // k per CTA
#define RT   256    // threads per CTA

// Scratch (static device memory — no runtime allocation)
__device__ float    g_buf0[(size_t)BB * SS * HH];   // 128 MB: xp0, then xp1
__device__ float    g_buf1[(size_t)BB * SS * HH];   // 128 MB: h0seq, then h1seq
__device__ float    g_part[(size_t)KSP * BB * HH];  // 8 MB split-K partials
__device__ unsigned g_bar[2 * SS];                  // per-step barrier counters

// ---------------------------------------------------------------------------
// Barrier counter reset (launched before each recurrence kernel)
// ---------------------------------------------------------------------------
__global__ void zero_bar_kernel() {
    int i = blockIdx.x * blockDim.x + threadIdx.x;
    if (i < 2 * SS) g_bar[i] = 0u;
}

// ---------------------------------------------------------------------------
// Grid-wide spin barrier among NCTA co-resident CTAs
// ---------------------------------------------------------------------------
__device__ __forceinline__ void grid_barrier(int ev) {
    __threadfence();          // release: make this CTA's global writes visible
    __syncthreads();
    if (threadIdx.x == 0) {
        unsigned prev = atomicAdd(&g_bar[ev], 1u);
        if (prev + 1u < (unsigned)NCTA) {
            volatile unsigned* p = (volatile unsigned*)&g_bar[ev];
            while (*p < (unsigned)NCTA) { __nanosleep(40); }
        }
        __threadfence();      // acquire
    }
    __syncthreads();
}

// ---------------------------------------------------------------------------
// Persistent recurrence kernel:
//   for t in [0, S): hseq[:,t,:] = tanh(xp[:,t,:] + hseq[:,t-1,:] @ Whh^T)
// CTA (jc, ks) computes partial sums over k-segment ks for j-chunk jc,
// then a reduction phase sums KSP partials + xp and applies tanh.
// ---------------------------------------------------------------------------
__global__ void __launch_bounds__(RT, 1) rnn_kernel(const float* __restrict__ xp,
                                                    float* __restrict__ hseq,
                                                    const float* __restrict__ Whh) {
    __shared__ float ws[KW][JW];       // 32 KB weight chunk, ws[k][j]
    __shared__ float hs[KW][BB + 4];   // h segment, hs[k][b]

    const int cta = blockIdx.x;
    const int jc  = cta & (JCH - 1);   // 0..3
    const int ks  = cta >> 2;          // 0..31
    const int J0  = jc * JW;
    const int K0  = ks * KW;
    const int tid = threadIdx.x;

    // Load weight chunk once: Whh[J0+j][K0+k] -> ws[k][j]
    {
        const float4* src = reinterpret_cast<const float4*>(Whh + (size_t)(J0 + tid) * HH + K0);
#pragma unroll
        for (int q = 0; q < 8; ++q) {
            float4 v = src[q];
            ws[q * 4 + 0][tid] = v.x;
            ws[q * 4 + 1][tid] = v.y;
            ws[q * 4 + 2][tid] = v.z;
            ws[q * 4 + 3][tid] = v.w;
        }
    }
    __syncthreads();

    // Compute-phase thread tile: 8 batches x 8 j (split as 4 + 4 for
    // conflict-free LDS.128: jA = tx*4, jB = 128 + tx*4)
    const int tx = tid & 31;
    const int ty = tid >> 5;
    const int b0 = ty * 8;
    const int jA = tx * 4;
    const int jB = 128 + tx * 4;

    // Reduction-phase element slice: 512 contiguous (b,j) elements per CTA
    const int e0 = cta * 512 + tid * 2;
    const int rb = e0 >> 10;
    const int rj = e0 & 1023;

    for (int t = 0; t < SS; ++t) {
        if (t > 0) {
            // Stage h segment: hseq[b][t-1][K0..K0+32) -> hs[k][b]
            {
                int b = tid >> 2;
                int q = tid & 3;
                const float4* src = reinterpret_cast<const float4*>(
                    hseq + ((size_t)b * SS + (t - 1)) * HH + K0 + q * 8);
                float4 v0 = __ldcg(src);
                float4 v1 = __ldcg(src + 1);
                int k = q * 8;
                hs[k + 0][b] = v0.x; hs[k + 1][b] = v0.y;
                hs[k + 2][b] = v0.z; hs[k + 3][b] = v0.w;
                hs[k + 4][b] = v1.x; hs[k + 5][b] = v1.y;
                hs[k + 6][b] = v1.z; hs[k + 7][b] = v1.w;
            }
            __syncthreads();

            float acc[8][8];
#pragma unroll
            for (int i = 0; i < 8; ++i)
#pragma unroll
                for (int c = 0; c < 8; ++c) acc[i][c] = 0.f;

#pragma unroll 8
            for (int k = 0; k < KW; ++k) {
                float4 h0 = *reinterpret_cast<const float4*>(&hs[k][b0]);
                float4 h1 = *reinterpret_cast<const float4*>(&hs[k][b0 + 4]);
                float4 w0 = *reinterpret_cast<const float4*>(&ws[k][jA]);
                float4 w1 = *reinterpret_cast<const float4*>(&ws[k][jB]);
                float hv[8] = {h0.x, h0.y, h0.z, h0.w, h1.x, h1.y, h1.z, h1.w};
                float wv[8] = {w0.x, w0.y, w0.z, w0.w, w1.x, w1.y, w1.z, w1.w};
#pragma unroll
                for (int i = 0; i < 8; ++i)
#pragma unroll
                    for (int c = 0; c < 8; ++c) acc[i][c] += hv[i] * wv[c];
            }

            // Write split-K partials: part[ks][b][j]
            float* pbase = g_part + (size_t)ks * BB * HH + (size_t)b0 * HH + J0;
#pragma unroll
            for (int i = 0; i < 8; ++i) {
                float4 pa = make_float4(acc[i][0], acc[i][1], acc[i][2], acc[i][3]);
                float4 pb = make_float4(acc[i][4], acc[i][5], acc[i][6], acc[i][7]);
                *reinterpret_cast<float4*>(pbase + (size_t)i * HH + jA) = pa;
                *reinterpret_cast<float4*>(pbase + (size_t)i * HH + jB) = pb;
            }
            __syncthreads();   // hs reuse safety for next iteration
        }

        grid_barrier(2 * t);

        // Reduction + activation for this CTA's 512-element slice
        {
            const float* xps = xp + ((size_t)rb * SS + t) * HH + rj;
            float v0 = __ldg(xps);
            float v1 = __ldg(xps + 1);
            if (t > 0) {
#pragma unroll
                for (int s = 0; s < KSP; ++s) {
                    float2 p = __ldcg(reinterpret_cast<const float2*>(
                        g_part + (size_t)s * BB * HH + e0));
                    v0 += p.x;
                    v1 += p.y;
                }
            }
            float* hdst = hseq + ((size_t)rb * SS + t) * HH + rj;
            hdst[0] = tanhf(v0);
            hdst[1] = tanhf(v1);
        }

        grid_barrier(2 * t + 1);
    }
}

// ---------------------------------------------------------------------------
// Tiled fp32 GEMM with bias:  C[M,N] = A[M,K] @ B[N,K]^T + bias1 + bias2
// BM=BN=128, BK=16, 256 threads, 8x8 register tiles (4+4 split fragments).
// M must be a multiple of 128, N a multiple of 128, K a multiple of 16.
// ---------------------------------------------------------------------------
__global__ void __launch_bounds__(256) gemm_bias_kernel(const float* __restrict__ A,
                                                        const float* __restrict__ Bm,
                                                        const float* __restrict__ bias1,
                                                        const float* __restrict__ bias2,
                                                        float* __restrict__ C,
                                                        int K, int N) {
    constexpr int BM = 128, BN = 128, BK = 16;
    __shared__ float As[BK][BM + 4];
    __shared__ float Bs[BK][BN + 4];

    const int tid   = threadIdx.x;
    const int mBase = blockIdx.y * BM;
    const int nBase = blockIdx.x * BN;
    const int tx = tid & 15;
    const int ty = tid >> 4;
    const int lr = tid >> 2;         // load row 0..63 (+64)
    const int lc = (tid & 3) * 4;    // k offset within tile

    float acc[8][8];
#pragma unroll
    for (int i = 0; i < 8; ++i)
#pragma unroll
        for (int c = 0; c < 8; ++c) acc[i][c] = 0.f;

    const int NT = K / BK;
    for (int kt = 0; kt < NT; ++kt) {
#pragma unroll
        for (int h = 0; h < 2; ++h) {
            int r = lr + h * 64;
            float4 va = *reinterpret_cast<const float4*>(
                A + (size_t)(mBase + r) * K + kt * BK + lc);
            As[lc + 0][r] = va.x; As[lc + 1][r] = va.y;
            As[lc + 2][r] = va.z; As[lc + 3][r] = va.w;
            float4 vb = *reinterpret_cast<const float4*>(
                Bm + (size_t)(nBase + r) * K + kt * BK + lc);
            Bs[lc + 0][r] = vb.x; Bs[lc + 1][r] = vb.y;
            Bs[lc + 2][r] = vb.z; Bs[lc + 3][r] = vb.w;
        }
        __syncthreads();

#pragma unroll
        for (int k = 0; k < BK; ++k) {
            float4 a0 = *reinterpret_cast<const float4*>(&As[k][ty * 4]);
            float4 a1 = *reinterpret_cast<const float4*>(&As[k][64 + ty * 4]);
            float4 b0 = *reinterpret_cast<const float4*>(&Bs[k][tx * 4]);
            float4 b1 = *reinterpret_cast<const float4*>(&Bs[k][64 + tx * 4]);
            float av[8] = {a0.x, a0.y, a0.z, a0.w, a1.x, a1.y, a1.z, a1.w};
            float bv[8] = {b0.x, b0.y, b0.z, b0.w, b1.x, b1.y, b1.z, b1.w};
#pragma unroll
            for (int i = 0; i < 8; ++i)
#pragma unroll
                for (int c = 0; c < 8; ++c) acc[i][c] += av[i] * bv[c];
        }
        __syncthreads();
    }

    // Epilogue: add biases, store as float4 pairs
    float bb[8];
#pragma unroll
    for (int c = 0; c < 8; ++c) {
        int n = nBase + ((c < 4) ? (tx * 4 + c) : (64 + tx * 4 + (c - 4)));
        float b = bias1[n];
        if (bias2) b += bias2[n];
        bb[c] = b;
    }
#pragma unroll
    for (int i = 0; i < 8; ++i) {
        int m = mBase + ((i < 4) ? (ty * 4 + i) : (64 + ty * 4 + (i - 4)));
        float4 oa = make_float4(acc[i][0] + bb[0], acc[i][1] + bb[1],
                                acc[i][2] + bb[2], acc[i][3] + bb[3]);
        float4 ob = make_float4(acc[i][4] + bb[4], acc[i][5] + bb[5],
                                acc[i][6] + bb[6], acc[i][7] + bb[7]);
        *reinterpret_cast<float4*>(C + (size_t)m * N + nBase + tx * 4) = oa;
        *reinterpret_cast<float4*>(C + (size_t)m * N + nBase + 64 + tx * 4) = ob;
    }
}

// ---------------------------------------------------------------------------
// Final FC: out[b,n] = hseq[b, S-1, :] . Wfc[n, :] + bfc[n]
// ---------------------------------------------------------------------------
__global__ void __launch_bounds__(128) fc_kernel(const float* __restrict__ hseq,
                                                 const float* __restrict__ Wfc,
                                                 const float* __restrict__ bfc,
                                                 float* __restrict__ out) {
    __shared__ float hsh[HH];
    const int b = blockIdx.x;
    const float* hrow = hseq + ((size_t)b * SS + (SS - 1)) * HH;
    for (int k = threadIdx.x; k < HH; k += 128) hsh[k] = hrow[k];
    __syncthreads();

    const int n = threadIdx.x;
    float acc = bfc[n];
    const float* w = Wfc + (size_t)n * HH;
#pragma unroll 8
    for (int k = 0; k < HH; ++k) acc += hsh[k] * __ldg(w + k);
    out[b * NOUT + n] = acc;
}

// ---------------------------------------------------------------------------
// Entry point
// ---------------------------------------------------------------------------
extern "C" void kernel_launch(void* const* d_in, const int* in_sizes, int n_in,
                              void* d_out, int out_size) {
    const float* x    = (const float*)d_in[0];
    const float* Wih0 = (const float*)d_in[1];
    const float* bih0 = (const float*)d_in[2];
    const float* Whh0 = (const float*)d_in[3];
    const float* bhh0 = (const float*)d_in[4];
    const float* Wih1 = (const float*)d_in[5];
    const float* bih1 = (const float*)d_in[6];
    const float* Whh1 = (const float*)d_in[7];
    const float* bhh1 = (const float*)d_in[8];
    const float* Wfc  = (const float*)d_in[9];
    const float* bfc  = (const float*)d_in[10];
    float* out = (float*)d_out;

    float *buf0 = nullptr, *buf1 = nullptr;
    cudaGetSymbolAddress((void**)&buf0, g_buf0);
    cudaGetSymbolAddress((void**)&buf1, g_buf1);

    dim3 gproj(HH / 128, (BB * SS) / 128);  // (8, 256)

    // Phase A: xp0 = x @ Wih0^T + bih0 + bhh0
    gemm_bias_kernel<<<gproj, 256>>>(x, Wih0, bih0, bhh0, buf0, NIN, HH);

    // Phase B: layer-0 recurrence -> h0seq in buf1
    zero_bar_kernel<<<4, 256>>>();
    rnn_kernel<<<NCTA, RT>>>(buf0, buf1, Whh0);

    // Phase C: xp1 = h0seq @ Wih1^T + bih1 + bhh1 (overwrites buf0)
    gemm_bias_kernel<<<gproj, 256>>>(buf1, Wih1, bih1, bhh1, buf0, HH, HH);

    // Phase D: layer-1 recurrence -> h1seq in buf1
    zero_bar_kernel<<<4, 256>>>();
    rnn_kernel<<<NCTA, RT>>>(buf0, buf1, Whh1);

    // Phase E: out = h1seq[:, S-1, :] @ Wfc^T + bfc
    fc_kernel<<<BB, 128>>>(buf1, Wfc, bfc, out);
}

// round 4
// speedup vs baseline: 1.0504x; 1.0504x over previous
#include <cuda_runtime.h>
#include <cuda_bf16.h>
#include <math.h>

// Problem constants
#define HH   1024
#define BB   64
#define SS   512
#define NIN  128
#define NOUT 128

// Recurrence kernel config: 128 persistent CTAs = JCH j-chunks x KSP k-splits
#define NCTA 128
#define JCH  4      // j chunks of 256
#define KSP  32     // k splits of 32
#define JW   256    // j per CTA
#define KW   32     // k per CTA
#define RT   256    // threads per CTA

typedef unsigned long long u64;

// Scratch (static device memory — no runtime allocation)
__device__ float    g_buf0[(size_t)BB * SS * HH];   // 128 MB: xp0, then xp1
__device__ float    g_buf1[(size_t)BB * SS * HH];   // 128 MB: h0seq, then h1seq
__device__ float    g_part[(size_t)KSP * BB * HH];  // 8 MB split-K partials
__device__ unsigned g_bar[2 * SS];                  // per-step barrier counters

// ---------------------------------------------------------------------------
// Packed fp32x2 helpers (SASS FFMA2 — only reachable via explicit PTX)
// ---------------------------------------------------------------------------
__device__ __forceinline__ u64 dupf2(float x) {
    u64 r;
    asm("mov.b64 %0, {%1, %1};" : "=l"(r) : "f"(x));
    return r;
}
__device__ __forceinline__ u64 packf2(float lo, float hi) {
    u64 r;
    asm("mov.b64 %0, {%1, %2};" : "=l"(r) : "f"(lo), "f"(hi));
    return r;
}
__device__ __forceinline__ void unpackf2(u64 v, float& lo, float& hi) {
    asm("mov.b64 {%0, %1}, %2;" : "=f"(lo), "=f"(hi) : "l"(v));
}
__device__ __forceinline__ void ffma2(u64& d, u64 a, u64 b) {
    asm("fma.rn.f32x2 %0, %1, %2, %0;" : "+l"(d) : "l"(a), "l"(b));
}
__device__ __forceinline__ u64 addf2(u64 a, u64 b) {
    u64 r;
    asm("add.rn.f32x2 %0, %1, %2;" : "=l"(r) : "l"(a), "l"(b));
    return r;
}

// ---------------------------------------------------------------------------
// Barrier counter reset (launched before each recurrence kernel)
// ---------------------------------------------------------------------------
__global__ void zero_bar_kernel() {
    int i = blockIdx.x * blockDim.x + threadIdx.x;
    if (i < 2 * SS) g_bar[i] = 0u;
}

// ---------------------------------------------------------------------------
// Grid-wide spin barrier among NCTA co-resident CTAs
// ---------------------------------------------------------------------------
__device__ __forceinline__ void grid_barrier(int ev) {
    __threadfence();          // release: make this CTA's global writes visible
    __syncthreads();
    if (threadIdx.x == 0) {
        unsigned prev = atomicAdd(&g_bar[ev], 1u);
        if (prev + 1u < (unsigned)NCTA) {
            volatile unsigned* p = (volatile unsigned*)&g_bar[ev];
            while (*p < (unsigned)NCTA) { __nanosleep(40); }
        }
        __threadfence();      // acquire
    }
    __syncthreads();
}

// ---------------------------------------------------------------------------
// Persistent recurrence kernel:
//   for t in [0, S): hseq[:,t,:] = tanh(xp[:,t,:] + hseq[:,t-1,:] @ Whh^T)
// CTA (jc, ks) computes partial sums over k-segment ks for j-chunk jc,
// then a reduction phase sums KSP partials + xp and applies tanh.
// Inner product uses packed fma.rn.f32x2 (FFMA2): 2 MACs per issue slot.
// ---------------------------------------------------------------------------
__global__ void __launch_bounds__(RT, 1) rnn_kernel(const float* __restrict__ xp,
                                                    float* __restrict__ hseq,
                                                    const float* __restrict__ Whh) {
    __shared__ float ws[KW][JW];       // 32 KB weight chunk, ws[k][j]
    __shared__ float hs[KW][BB + 4];   // h segment, hs[k][b]

    const int cta = blockIdx.x;
    const int jc  = cta & (JCH - 1);   // 0..3
    const int ks  = cta >> 2;          // 0..31
    const int J0  = jc * JW;
    const int K0  = ks * KW;
    const int tid = threadIdx.x;

    // Load weight chunk once: Whh[J0+j][K0+k] -> ws[k][j]
    {
        const float4* src = reinterpret_cast<const float4*>(Whh + (size_t)(J0 + tid) * HH + K0);
#pragma unroll
        for (int q = 0; q < 8; ++q) {
            float4 v = src[q];
            ws[q * 4 + 0][tid] = v.x;
            ws[q * 4 + 1][tid] = v.y;
            ws[q * 4 + 2][tid] = v.z;
            ws[q * 4 + 3][tid] = v.w;
        }
    }
    __syncthreads();

    // Compute-phase thread tile: 8 batches x 8 j (split as 4 + 4 for
    // conflict-free LDS.128: jA = tx*4, jB = 128 + tx*4)
    const int tx = tid & 31;
    const int ty = tid >> 5;
    const int b0 = ty * 8;
    const int jA = tx * 4;
    const int jB = 128 + tx * 4;

    // Reduction-phase element slice: 512 contiguous (b,j) elements per CTA
    const int e0 = cta * 512 + tid * 2;
    const int rb = e0 >> 10;
    const int rj = e0 & 1023;

    for (int t = 0; t < SS; ++t) {
        if (t > 0) {
            // Stage h segment: hseq[b][t-1][K0..K0+32) -> hs[k][b]
            {
                int b = tid >> 2;
                int q = tid & 3;
                const float4* src = reinterpret_cast<const float4*>(
                    hseq + ((size_t)b * SS + (t - 1)) * HH + K0 + q * 8);
                float4 v0 = __ldcg(src);
                float4 v1 = __ldcg(src + 1);
                int k = q * 8;
                hs[k + 0][b] = v0.x; hs[k + 1][b] = v0.y;
                hs[k + 2][b] = v0.z; hs[k + 3][b] = v0.w;
                hs[k + 4][b] = v1.x; hs[k + 5][b] = v1.y;
                hs[k + 6][b] = v1.z; hs[k + 7][b] = v1.w;
            }
            __syncthreads();

            // acc[i][p]: batch i (8), j-pair p (4): p=0,1 -> jA+(0,1),(2,3)
            //                                      p=2,3 -> jB+(0,1),(2,3)
            u64 acc[8][4];
#pragma unroll
            for (int i = 0; i < 8; ++i)
#pragma unroll
                for (int p = 0; p < 4; ++p) acc[i][p] = 0ull;

#pragma unroll 8
            for (int k = 0; k < KW; ++k) {
                float4 h0 = *reinterpret_cast<const float4*>(&hs[k][b0]);
                float4 h1 = *reinterpret_cast<const float4*>(&hs[k][b0 + 4]);
                ulonglong2 wA = *reinterpret_cast<const ulonglong2*>(&ws[k][jA]);
                ulonglong2 wB = *reinterpret_cast<const ulonglong2*>(&ws[k][jB]);
                u64 hd[8];
                hd[0] = dupf2(h0.x); hd[1] = dupf2(h0.y);
                hd[2] = dupf2(h0.z); hd[3] = dupf2(h0.w);
                hd[4] = dupf2(h1.x); hd[5] = dupf2(h1.y);
                hd[6] = dupf2(h1.z); hd[7] = dupf2(h1.w);
#pragma unroll
                for (int i = 0; i < 8; ++i) {
                    ffma2(acc[i][0], hd[i], wA.x);
                    ffma2(acc[i][1], hd[i], wA.y);
                    ffma2(acc[i][2], hd[i], wB.x);
                    ffma2(acc[i][3], hd[i], wB.y);
                }
            }

            // Write split-K partials: part[ks][b][j]  (direct 16B pair stores)
            float* pbase = g_part + (size_t)ks * BB * HH + (size_t)b0 * HH + J0;
#pragma unroll
            for (int i = 0; i < 8; ++i) {
                ulonglong2 pa; pa.x = acc[i][0]; pa.y = acc[i][1];
                ulonglong2 pb; pb.x = acc[i][2]; pb.y = acc[i][3];
                *reinterpret_cast<ulonglong2*>(pbase + (size_t)i * HH + jA) = pa;
                *reinterpret_cast<ulonglong2*>(pbase + (size_t)i * HH + jB) = pb;
            }
            __syncthreads();   // hs reuse safety for next iteration
        }

        grid_barrier(2 * t);

        // Reduction + activation for this CTA's 512-element slice
        {
            const float* xps = xp + ((size_t)rb * SS + t) * HH + rj;
            float v0 = __ldg(xps);
            float v1 = __ldg(xps + 1);
            if (t > 0) {
#pragma unroll
                for (int s = 0; s < KSP; ++s) {
                    float2 p = __ldcg(reinterpret_cast<const float2*>(
                        g_part + (size_t)s * BB * HH + e0));
                    v0 += p.x;
                    v1 += p.y;
                }
            }
            float* hdst = hseq + ((size_t)rb * SS + t) * HH + rj;
            hdst[0] = tanhf(v0);
            hdst[1] = tanhf(v1);
        }

        grid_barrier(2 * t + 1);
    }
}

// ---------------------------------------------------------------------------
// Tiled fp32 GEMM with bias:  C[M,N] = A[M,K] @ B[N,K]^T + bias1 + bias2
// BM=BN=128, BK=16, 256 threads, 8x8 register tiles (4+4 split fragments),
// packed fma.rn.f32x2 inner product.
// M must be a multiple of 128, N a multiple of 128, K a multiple of 16.
// ---------------------------------------------------------------------------
__global__ void __launch_bounds__(256) gemm_bias_kernel(const float* __restrict__ A,
                                                        const float* __restrict__ Bm,
                                                        const float* __restrict__ bias1,
                                                        const float* __restrict__ bias2,
                                                        float* __restrict__ C,
                                                        int K, int N) {
    constexpr int BM = 128, BN = 128, BK = 16;
    __shared__ float As[BK][BM + 4];   // row stride 132*4 = 528 B (16B aligned)
    __shared__ float Bs[BK][BN + 4];

    const int tid   = threadIdx.x;
    const int mBase = blockIdx.y * BM;
    const int nBase = blockIdx.x * BN;
    const int tx = tid & 15;
    const int ty = tid >> 4;
    const int lr = tid >> 2;         // load row 0..63 (+64)
    const int lc = (tid & 3) * 4;    // k offset within tile

    // acc[i][p]: a-row i (8), b-pair p (4)
    u64 acc[8][4];
#pragma unroll
    for (int i = 0; i < 8; ++i)
#pragma unroll
        for (int p = 0; p < 4; ++p) acc[i][p] = 0ull;

    const int NT = K / BK;
    for (int kt = 0; kt < NT; ++kt) {
#pragma unroll
        for (int h = 0; h < 2; ++h) {
            int r = lr + h * 64;
            float4 va = *reinterpret_cast<const float4*>(
                A + (size_t)(mBase + r) * K + kt * BK + lc);
            As[lc + 0][r] = va.x; As[lc + 1][r] = va.y;
            As[lc + 2][r] = va.z; As[lc + 3][r] = va.w;
            float4 vb = *reinterpret_cast<const float4*>(
                Bm + (size_t)(nBase + r) * K + kt * BK + lc);
            Bs[lc + 0][r] = vb.x; Bs[lc + 1][r] = vb.y;
            Bs[lc + 2][r] = vb.z; Bs[lc + 3][r] = vb.w;
        }
        __syncthreads();

#pragma unroll
        for (int k = 0; k < BK; ++k) {
            float4 a0 = *reinterpret_cast<const float4*>(&As[k][ty * 4]);
            float4 a1 = *reinterpret_cast<const float4*>(&As[k][64 + ty * 4]);
            ulonglong2 bA = *reinterpret_cast<const ulonglong2*>(&Bs[k][tx * 4]);
            ulonglong2 bB = *reinterpret_cast<const ulonglong2*>(&Bs[k][64 + tx * 4]);
            u64 ad[8];
            ad[0] = dupf2(a0.x); ad[1] = dupf2(a0.y);
            ad[2] = dupf2(a0.z); ad[3] = dupf2(a0.w);
            ad[4] = dupf2(a1.x); ad[5] = dupf2(a1.y);
            ad[6] = dupf2(a1.z); ad[7] = dupf2(a1.w);
#pragma unroll
            for (int i = 0; i < 8; ++i) {
                ffma2(acc[i][0], ad[i], bA.x);
                ffma2(acc[i][1], ad[i], bA.y);
                ffma2(acc[i][2], ad[i], bB.x);
                ffma2(acc[i][3], ad[i], bB.y);
            }
        }
        __syncthreads();
    }

    // Epilogue: add biases as packed pairs, 16B stores
    u64 bb[4];
#pragma unroll
    for (int p = 0; p < 4; ++p) {
        int n = nBase + ((p < 2) ? (tx * 4 + p * 2) : (64 + tx * 4 + (p - 2) * 2));
        float v0 = bias1[n];
        float v1 = bias1[n + 1];
        if (bias2) { v0 += bias2[n]; v1 += bias2[n + 1]; }
        bb[p] = packf2(v0, v1);
    }
#pragma unroll
    for (int i = 0; i < 8; ++i) {
        int m = mBase + ((i < 4) ? (ty * 4 + i) : (64 + ty * 4 + (i - 4)));
        ulonglong2 oa, ob;
        oa.x = addf2(acc[i][0], bb[0]); oa.y = addf2(acc[i][1], bb[1]);
        ob.x = addf2(acc[i][2], bb[2]); ob.y = addf2(acc[i][3], bb[3]);
        *reinterpret_cast<ulonglong2*>(C + (size_t)m * N + nBase + tx * 4) = oa;
        *reinterpret_cast<ulonglong2*>(C + (size_t)m * N + nBase + 64 + tx * 4) = ob;
    }
}

// ---------------------------------------------------------------------------
// Final FC: out[b,n] = hseq[b, S-1, :] . Wfc[n, :] + bfc[n]
// ---------------------------------------------------------------------------
__global__ void __launch_bounds__(128) fc_kernel(const float* __restrict__ hseq,
                                                 const float* __restrict__ Wfc,
                                                 const float* __restrict__ bfc,
                                                 float* __restrict__ out) {
    __shared__ float hsh[HH];
    const int b = blockIdx.x;
    const float* hrow = hseq + ((size_t)b * SS + (SS - 1)) * HH;
    for (int k = threadIdx.x; k < HH; k += 128) hsh[k] = hrow[k];
    __syncthreads();

    const int n = threadIdx.x;
    float acc = bfc[n];
    const float* w = Wfc + (size_t)n * HH;
#pragma unroll 8
    for (int k = 0; k < HH; ++k) acc += hsh[k] * __ldg(w + k);
    out[b * NOUT + n] = acc;
}

// ---------------------------------------------------------------------------
// Entry point
// ---------------------------------------------------------------------------
extern "C" void kernel_launch(void* const* d_in, const int* in_sizes, int n_in,
                              void* d_out, int out_size) {
    const float* x    = (const float*)d_in[0];
    const float* Wih0 = (const float*)d_in[1];
    const float* bih0 = (const float*)d_in[2];
    const float* Whh0 = (const float*)d_in[3];
    const float* bhh0 = (const float*)d_in[4];
    const float* Wih1 = (const float*)d_in[5];
    const float* bih1 = (const float*)d_in[6];
    const float* Whh1 = (const float*)d_in[7];
    const float* bhh1 = (const float*)d_in[8];
    const float* Wfc  = (const float*)d_in[9];
    const float* bfc  = (const float*)d_in[10];
    float* out = (float*)d_out;

    float *buf0 = nullptr, *buf1 = nullptr;
    cudaGetSymbolAddress((void**)&buf0, g_buf0);
    cudaGetSymbolAddress((void**)&buf1, g_buf1);

    dim3 gproj(HH / 128, (BB * SS) / 128);  // (8, 256)

    // Phase A: xp0 = x @ Wih0^T + bih0 + bhh0
    gemm_bias_kernel<<<gproj, 256>>>(x, Wih0, bih0, bhh0, buf0, NIN, HH);

    // Phase B: layer-0 recurrence -> h0seq in buf1
    zero_bar_kernel<<<4, 256>>>();
    rnn_kernel<<<NCTA, RT>>>(buf0, buf1, Whh0);

    // Phase C: xp1 = h0seq @ Wih1^T + bih1 + bhh1 (overwrites buf0)
    gemm_bias_kernel<<<gproj, 256>>>(buf1, Wih1, bih1, bhh1, buf0, HH, HH);

    // Phase D: layer-1 recurrence -> h1seq in buf1
    zero_bar_kernel<<<4, 256>>>();
    rnn_kernel<<<NCTA, RT>>>(buf0, buf1, Whh1);

    // Phase E: out = h1seq[:, S-1, :] @ Wfc^T + bfc
    fc_kernel<<<BB, 128>>>(buf1, Wfc, bfc, out);
}